// round 1
// baseline (speedup 1.0000x reference)
#include <cuda_runtime.h>

// Problem constants
#define B_     256
#define L_     512
#define E_     256
#define TWO_E  512
#define NODES  1023                // 2L-1
#define SB     (NODES * E_)        // 261888 floats per batch
#define C_     5

// Scratch: all node states, layout (B, 1023, E) row-major. 268 MB.
__device__ float g_states[(size_t)B_ * NODES * E_];

// ---------------------------------------------------------------------------
// Kernel 1: leaves — h = relu(emb[words]) into level-0 slots of g_states.
// One warp per row (256 floats = 64 float4, 2 per lane).
// ---------------------------------------------------------------------------
__global__ __launch_bounds__(256)
void leaf_kernel(const int* __restrict__ words, const float* __restrict__ emb) {
    int r    = blockIdx.x * 8 + (threadIdx.x >> 5);   // global leaf row = b*L + i
    int lane = threadIdx.x & 31;
    int w = __ldg(&words[r]);
    const float4* src = reinterpret_cast<const float4*>(emb + (size_t)w * E_);
    int b = r >> 9;            // / L_
    int i = r & (L_ - 1);
    float4* dst = reinterpret_cast<float4*>(g_states + (size_t)b * SB + (size_t)i * E_);
#pragma unroll
    for (int j = 0; j < 2; j++) {
        float4 v = src[lane + 32 * j];
        v.x = fmaxf(v.x, 0.f); v.y = fmaxf(v.y, 0.f);
        v.z = fmaxf(v.z, 0.f); v.w = fmaxf(v.w, 0.f);
        dst[lane + 32 * j] = v;
    }
}

// ---------------------------------------------------------------------------
// Kernel 2: one tree level — out = relu(X @ W^T + bias), X = (M x 512),
// W row-major (256 x 512). Adjacent siblings are contiguous in g_states, so
// X rows are just 512-float slices. Rows per batch is a power of two (2^lg),
// so row -> (batch, idx) is shift/mask.
// Classic SGEMM: BM=BN=128, BK=8, 256 threads, 8x8 microtile.
// M is always a multiple of 128 and N == 256 == 2*128: no bounds checks.
// ---------------------------------------------------------------------------
__global__ __launch_bounds__(256, 2)
void compose_gemm(const float* __restrict__ W, const float* __restrict__ bias,
                  int in_off, int out_off, int lg) {
    __shared__ float As[8][128];
    __shared__ float Bs[8][128];

    const int tid      = threadIdx.x;
    const int blockRow = blockIdx.x * 128;
    const int colBase  = blockIdx.y * 128;

    // A-tile load mapping: thread -> (row ar, 4 consecutive k)
    const int ar = tid >> 1;
    const int ak = (tid & 1) * 4;
    const int gr = blockRow + ar;
    const int ab = gr >> lg;
    const int ai = gr & ((1 << lg) - 1);
    const float* arow = g_states + (size_t)ab * SB + (size_t)in_off * E_
                                 + (size_t)ai * TWO_E;

    // B-tile load mapping: thread -> (W row bn within col block, 4 consecutive k)
    const int bn = tid >> 1;
    const int bk = (tid & 1) * 4;
    const float* wrow = W + (size_t)(colBase + bn) * TWO_E;

    const int ty    = tid >> 4;        // 0..15
    const int tx    = tid & 15;        // 0..15
    const int mBase = ty * 8;
    const int nBase = tx * 8;

    float acc[8][8];
#pragma unroll
    for (int m = 0; m < 8; m++)
#pragma unroll
        for (int n = 0; n < 8; n++) acc[m][n] = 0.f;

    for (int k0 = 0; k0 < TWO_E; k0 += 8) {
        float4 av = *reinterpret_cast<const float4*>(arow + k0 + ak);
        float4 bv = *reinterpret_cast<const float4*>(wrow + k0 + bk);
        __syncthreads();                       // prev tile fully consumed
        As[ak + 0][ar] = av.x; As[ak + 1][ar] = av.y;
        As[ak + 2][ar] = av.z; As[ak + 3][ar] = av.w;
        Bs[bk + 0][bn] = bv.x; Bs[bk + 1][bn] = bv.y;
        Bs[bk + 2][bn] = bv.z; Bs[bk + 3][bn] = bv.w;
        __syncthreads();
#pragma unroll
        for (int k = 0; k < 8; k++) {
            float a[8], bb[8];
            *reinterpret_cast<float4*>(a)      = *reinterpret_cast<const float4*>(&As[k][mBase]);
            *reinterpret_cast<float4*>(a + 4)  = *reinterpret_cast<const float4*>(&As[k][mBase + 4]);
            *reinterpret_cast<float4*>(bb)     = *reinterpret_cast<const float4*>(&Bs[k][nBase]);
            *reinterpret_cast<float4*>(bb + 4) = *reinterpret_cast<const float4*>(&Bs[k][nBase + 4]);
#pragma unroll
            for (int m = 0; m < 8; m++)
#pragma unroll
                for (int n = 0; n < 8; n++)
                    acc[m][n] = fmaf(a[m], bb[n], acc[m][n]);
        }
    }

    float bv0[8];
#pragma unroll
    for (int n = 0; n < 8; n++) bv0[n] = bias[colBase + nBase + n];

#pragma unroll
    for (int m = 0; m < 8; m++) {
        int gr2 = blockRow + mBase + m;
        int b2  = gr2 >> lg;
        int i2  = gr2 & ((1 << lg) - 1);
        float* orow = g_states + (size_t)b2 * SB
                               + (size_t)(out_off + i2) * E_ + colBase + nBase;
        float4 o0, o1;
        o0.x = fmaxf(acc[m][0] + bv0[0], 0.f);
        o0.y = fmaxf(acc[m][1] + bv0[1], 0.f);
        o0.z = fmaxf(acc[m][2] + bv0[2], 0.f);
        o0.w = fmaxf(acc[m][3] + bv0[3], 0.f);
        o1.x = fmaxf(acc[m][4] + bv0[4], 0.f);
        o1.y = fmaxf(acc[m][5] + bv0[5], 0.f);
        o1.z = fmaxf(acc[m][6] + bv0[6], 0.f);
        o1.w = fmaxf(acc[m][7] + bv0[7], 0.f);
        *reinterpret_cast<float4*>(orow)     = o0;
        *reinterpret_cast<float4*>(orow + 4) = o1;
    }
}

// ---------------------------------------------------------------------------
// Kernel 3: projection — out[r, c] = dot(states[r,:], P[c,:]) + pb[c].
// One warp per row; P (5x256 = 5 KB) staged in smem; warp shuffle reduction.
// ---------------------------------------------------------------------------
__global__ __launch_bounds__(256)
void proj_kernel(const float* __restrict__ P, const float* __restrict__ pb,
                 float* __restrict__ out) {
    __shared__ float Ps[C_ * E_];
    for (int idx = threadIdx.x; idx < C_ * E_; idx += 256) Ps[idx] = P[idx];
    __syncthreads();

    int r    = blockIdx.x * 8 + (threadIdx.x >> 5);
    int lane = threadIdx.x & 31;
    const float* row = g_states + (size_t)r * E_;
    float4 v0 = reinterpret_cast<const float4*>(row)[lane];
    float4 v1 = reinterpret_cast<const float4*>(row)[lane + 32];
    float x[8] = {v0.x, v0.y, v0.z, v0.w, v1.x, v1.y, v1.z, v1.w};
    const int e0 = lane * 4;
    const int e1 = 128 + lane * 4;

    float acc[C_];
#pragma unroll
    for (int c = 0; c < C_; c++) {
        const float* pc = &Ps[c * E_];
        float s = 0.f;
#pragma unroll
        for (int t = 0; t < 4; t++) s = fmaf(x[t],     pc[e0 + t], s);
#pragma unroll
        for (int t = 0; t < 4; t++) s = fmaf(x[4 + t], pc[e1 + t], s);
        acc[c] = s;
    }
#pragma unroll
    for (int c = 0; c < C_; c++) {
#pragma unroll
        for (int o = 16; o > 0; o >>= 1)
            acc[c] += __shfl_xor_sync(0xffffffffu, acc[c], o);
    }
    if (lane == 0) {
#pragma unroll
        for (int c = 0; c < C_; c++)
            out[(size_t)r * C_ + c] = acc[c] + pb[c];
    }
}

// ---------------------------------------------------------------------------
// Launch: leaves -> 9 level GEMMs -> projection. All plain kernel launches
// on the capture stream; no sync, no allocation.
// ---------------------------------------------------------------------------
extern "C" void kernel_launch(void* const* d_in, const int* in_sizes, int n_in,
                              void* d_out, int out_size) {
    const int*   words = (const int*)  d_in[0];
    const float* emb   = (const float*)d_in[1];
    const float* W     = (const float*)d_in[2];
    const float* bias  = (const float*)d_in[3];
    const float* P     = (const float*)d_in[4];
    const float* pb    = (const float*)d_in[5];
    float*       out   = (float*)d_out;

    leaf_kernel<<<(B_ * L_) / 8, 256>>>(words, emb);

    int off = 0, n = L_;
    for (int l = 0; l < 9; l++) {
        int rpb = n >> 1;                 // rows per batch at this level
        int lg  = 8 - l;                  // log2(rpb)
        int M   = B_ * rpb;
        dim3 grid(M / 128, E_ / 128);
        compose_gemm<<<grid, 256>>>(W, bias, off, off + n, lg);
        off += n;
        n >>= 1;
    }

    proj_kernel<<<(B_ * NODES) / 8, 256>>>(P, pb, out);
}

// round 3
// speedup vs baseline: 2.0385x; 2.0385x over previous
#include <cuda_runtime.h>
#include <cuda_bf16.h>
#include <cstdint>

// ---------------------------------------------------------------------------
// Problem constants
// ---------------------------------------------------------------------------
#define B_     256
#define L_     512
#define E_     256
#define TWO_E  512
#define NODES  1023
#define SB     (NODES * E_)
#define C_     5

// Node states as split bf16 planes: value = hi + lo (~16 mantissa bits).
__device__ __nv_bfloat16 g_shi[(size_t)B_ * NODES * E_];
__device__ __nv_bfloat16 g_slo[(size_t)B_ * NODES * E_];
// W split into bf16 hi/lo, row-major (256 x 512).
__device__ __nv_bfloat16 g_Whi[E_ * TWO_E];
__device__ __nv_bfloat16 g_Wlo[E_ * TWO_E];

// ---------------------------------------------------------------------------
// Helpers
// ---------------------------------------------------------------------------
__device__ __forceinline__ uint32_t smem_u32(const void* p) {
    uint32_t a;
    asm("{ .reg .u64 t; cvta.to.shared.u64 t, %1; cvt.u32.u64 %0, t; }" : "=r"(a) : "l"(p));
    return a;
}
__device__ __forceinline__ uint32_t pkbf(__nv_bfloat16 a, __nv_bfloat16 b) {
    return (uint32_t)__bfloat16_as_ushort(a) | ((uint32_t)__bfloat16_as_ushort(b) << 16);
}

#define CP16(dst, src) \
    asm volatile("cp.async.ca.shared.global [%0], [%1], 16;" :: "r"(dst), "l"(src))
#define CP_COMMIT() asm volatile("cp.async.commit_group;" ::: "memory")

#define LDSM_X4(r, addr)                                                        \
    asm volatile("ldmatrix.sync.aligned.m8n8.x4.shared.b16 {%0,%1,%2,%3}, [%4];" \
        : "=r"((r)[0]), "=r"((r)[1]), "=r"((r)[2]), "=r"((r)[3]) : "r"(addr))

#define MMA16816(acc, a, b)                                                     \
    asm volatile("mma.sync.aligned.m16n8k16.row.col.f32.bf16.bf16.f32 "         \
        "{%0,%1,%2,%3}, {%4,%5,%6,%7}, {%8,%9}, {%0,%1,%2,%3};"                 \
        : "+f"((acc)[0]), "+f"((acc)[1]), "+f"((acc)[2]), "+f"((acc)[3])        \
        : "r"((a)[0]), "r"((a)[1]), "r"((a)[2]), "r"((a)[3]),                   \
          "r"((b)[0]), "r"((b)[1]))

// ---------------------------------------------------------------------------
// SMEM layout for the GEMM
// ---------------------------------------------------------------------------
#define BM 128
#define BN 128
#define BK 32
#define ROWB 80                       // bytes per smem row: 32 bf16 + 8 pad
#define PLANE 10240                   // 128 rows * 80 B
#define OFF_AH 0
#define OFF_AL PLANE
#define OFF_BH (2 * PLANE)
#define OFF_BL (3 * PLANE)
#define STAGE_BYTES (4 * PLANE)       // 40960
#define SM_BIAS_OFF (2 * STAGE_BYTES) // 81920
#define SMEM_TOTAL (SM_BIAS_OFF + 512)

// ---------------------------------------------------------------------------
// W split kernel: fp32 -> (hi, lo) bf16
// ---------------------------------------------------------------------------
__global__ void wsplit_kernel(const float* __restrict__ W) {
    int i = blockIdx.x * 256 + threadIdx.x;
    float f = W[i];
    __nv_bfloat16 h = __float2bfloat16(f);
    g_Whi[i] = h;
    g_Wlo[i] = __float2bfloat16(f - __bfloat162float(h));
}

// ---------------------------------------------------------------------------
// Leaves: relu(emb[word]) -> hi/lo planes
// ---------------------------------------------------------------------------
__global__ __launch_bounds__(256)
void leaf_kernel(const int* __restrict__ words, const float* __restrict__ emb) {
    int r    = blockIdx.x * 8 + (threadIdx.x >> 5);
    int lane = threadIdx.x & 31;
    int w = __ldg(&words[r]);
    const float4* src = reinterpret_cast<const float4*>(emb + (size_t)w * E_);
    float4 v0 = src[lane * 2], v1 = src[lane * 2 + 1];
    float f[8] = {v0.x, v0.y, v0.z, v0.w, v1.x, v1.y, v1.z, v1.w};
    uint32_t hi[4], lo[4];
#pragma unroll
    for (int p = 0; p < 4; p++) {
        float a = fmaxf(f[2 * p], 0.f), b = fmaxf(f[2 * p + 1], 0.f);
        __nv_bfloat16 ha = __float2bfloat16(a), hb = __float2bfloat16(b);
        hi[p] = pkbf(ha, hb);
        lo[p] = pkbf(__float2bfloat16(a - __bfloat162float(ha)),
                     __float2bfloat16(b - __bfloat162float(hb)));
    }
    size_t off = (size_t)(r >> 9) * SB + (size_t)(r & 511) * E_ + lane * 8;
    *reinterpret_cast<uint4*>(g_shi + off) = make_uint4(hi[0], hi[1], hi[2], hi[3]);
    *reinterpret_cast<uint4*>(g_slo + off) = make_uint4(lo[0], lo[1], lo[2], lo[3]);
}

// ---------------------------------------------------------------------------
// Compose GEMM on tensor cores (mma.sync bf16, split hi/lo, 3 products).
// out = relu(X @ W^T + bias); X rows are concat'd sibling pairs (512 wide).
// CTA tile 128x128 (grid.y = 2 covers N=256), 8 warps (4x2), warp tile 32x64.
// 2-stage cp.async pipeline over K=512 in BK=32 chunks.
// ---------------------------------------------------------------------------
__global__ __launch_bounds__(256, 1)
void mma_gemm(const float* __restrict__ bias, int in_off, int out_off, int lg) {
    extern __shared__ char smem[];
    const uint32_t sb = smem_u32(smem);
    const int tid  = threadIdx.x;
    const int lane = tid & 31;
    const int warp = tid >> 5;
    const int warpM = warp & 3;     // 4 warps over M
    const int warpN = warp >> 2;    // 2 warps over N
    const int blockRow = blockIdx.x * BM;
    const int colBase  = blockIdx.y * BN;
    const int msk = (1 << lg) - 1;

    if (tid < 128)
        reinterpret_cast<float*>(smem + SM_BIAS_OFF)[tid] = bias[colBase + tid];

    // --- per-thread cp.async chunk descriptors (8 x 16B per stage) ---
    const __nv_bfloat16* srcs[8];
    uint32_t dsts[8];
#pragma unroll
    for (int j = 0; j < 8; j++) {
        int c = tid + 256 * j;
        if (c < 1024) {                 // A: 128 rows x 64B x 2 planes
            int plane = c >> 9, row = (c >> 2) & 127, seg = c & 3;
            int gr = blockRow + row, ab = gr >> lg, ai = gr & msk;
            const __nv_bfloat16* g = plane ? g_slo : g_shi;
            srcs[j] = g + (size_t)ab * SB + (size_t)in_off * E_
                        + (size_t)ai * TWO_E + seg * 8;
            dsts[j] = (plane ? OFF_AL : OFF_AH) + row * ROWB + seg * 16;
        } else {                        // B: 128 W-rows x 64B x 2 planes
            int c2 = c - 1024;
            int plane = c2 >> 9, row = (c2 >> 2) & 127, seg = c2 & 3;
            const __nv_bfloat16* g = plane ? g_Wlo : g_Whi;
            srcs[j] = g + (size_t)(colBase + row) * TWO_E + seg * 8;
            dsts[j] = (plane ? OFF_BL : OFF_BH) + row * ROWB + seg * 16;
        }
    }

#define ISSUE(it) do {                                              \
        uint32_t _base = sb + ((it) & 1) * STAGE_BYTES;             \
        int _k0 = (it) * BK;                                        \
        _Pragma("unroll")                                           \
        for (int _j = 0; _j < 8; _j++)                              \
            CP16(_base + dsts[_j], srcs[_j] + _k0);                 \
        CP_COMMIT();                                                \
    } while (0)

    ISSUE(0);
    ISSUE(1);

    float acc[2][8][4];
#pragma unroll
    for (int mt = 0; mt < 2; mt++)
#pragma unroll
        for (int nt = 0; nt < 8; nt++)
#pragma unroll
            for (int q = 0; q < 4; q++) acc[mt][nt][q] = 0.f;

    // ldmatrix lane-address components
    const int aRow     = warpM * 32 + ((lane >> 3) & 1) * 8 + (lane & 7);
    const int aColHalf = (lane >> 4);          // *8 k
    const int bRow     = warpN * 64 + ((lane >> 4) << 3) + (lane & 7);
    const int bColHalf = (lane >> 3) & 1;      // *8 k

    for (int it = 0; it < 16; ++it) {
        if (it < 14) asm volatile("cp.async.wait_group 1;" ::: "memory");
        else         asm volatile("cp.async.wait_group 0;" ::: "memory");
        __syncthreads();
        uint32_t base = sb + (it & 1) * STAGE_BYTES;

#pragma unroll
        for (int kk = 0; kk < 2; kk++) {
            uint32_t Ah[2][4], Al[2][4], Bh[8][2], Bl[8][2];
#pragma unroll
            for (int mt = 0; mt < 2; mt++) {
                uint32_t addr = base + (uint32_t)((aRow + mt * 16) * ROWB
                              + (kk * 16 + aColHalf * 8) * 2);
                LDSM_X4(Ah[mt], addr + OFF_AH);
                LDSM_X4(Al[mt], addr + OFF_AL);
            }
#pragma unroll
            for (int ntp = 0; ntp < 4; ntp++) {
                uint32_t addr = base + (uint32_t)((bRow + ntp * 16) * ROWB
                              + (kk * 16 + bColHalf * 8) * 2);
                uint32_t r0[4], r1[4];
                LDSM_X4(r0, addr + OFF_BH);
                LDSM_X4(r1, addr + OFF_BL);
                Bh[2 * ntp][0] = r0[0]; Bh[2 * ntp][1] = r0[1];
                Bh[2 * ntp + 1][0] = r0[2]; Bh[2 * ntp + 1][1] = r0[3];
                Bl[2 * ntp][0] = r1[0]; Bl[2 * ntp][1] = r1[1];
                Bl[2 * ntp + 1][0] = r1[2]; Bl[2 * ntp + 1][1] = r1[3];
            }
#pragma unroll
            for (int mt = 0; mt < 2; mt++)
#pragma unroll
                for (int nt = 0; nt < 8; nt++) {
                    MMA16816(acc[mt][nt], Ah[mt], Bh[nt]);
                    MMA16816(acc[mt][nt], Ah[mt], Bl[nt]);
                    MMA16816(acc[mt][nt], Al[mt], Bh[nt]);
                }
        }
        __syncthreads();
        if (it + 2 < 16) ISSUE(it + 2);
    }

    // --- epilogue: +bias, relu, split to hi/lo, store ---
    const float* sbias = reinterpret_cast<const float*>(smem + SM_BIAS_OFF);
    const int nOff = warpN * 64 + (lane & 3) * 2;   // local col
#pragma unroll
    for (int mt = 0; mt < 2; mt++) {
        int rl = warpM * 32 + mt * 16 + (lane >> 2);
#pragma unroll
        for (int h = 0; h < 2; h++) {
            int gro = blockRow + rl + 8 * h;
            int ob = gro >> lg, oi = gro & msk;
            size_t rowoff = (size_t)ob * SB + (size_t)(out_off + oi) * E_
                          + colBase + nOff;
            uint32_t* dh = reinterpret_cast<uint32_t*>(g_shi + rowoff);
            uint32_t* dl = reinterpret_cast<uint32_t*>(g_slo + rowoff);
#pragma unroll
            for (int nt = 0; nt < 8; nt++) {
                float v0 = fmaxf(acc[mt][nt][2 * h]     + sbias[nOff + nt * 8], 0.f);
                float v1 = fmaxf(acc[mt][nt][2 * h + 1] + sbias[nOff + nt * 8 + 1], 0.f);
                __nv_bfloat16 h0 = __float2bfloat16(v0), h1 = __float2bfloat16(v1);
                dh[nt * 4] = pkbf(h0, h1);
                dl[nt * 4] = pkbf(__float2bfloat16(v0 - __bfloat162float(h0)),
                                  __float2bfloat16(v1 - __bfloat162float(h1)));
            }
        }
    }
#undef ISSUE
}

// ---------------------------------------------------------------------------
// Projection: out[r, c] = dot(hi[r]+lo[r], P[c]) + pb[c]
// ---------------------------------------------------------------------------
__global__ __launch_bounds__(256)
void proj_kernel(const float* __restrict__ P, const float* __restrict__ pb,
                 float* __restrict__ out) {
    __shared__ float Ps[C_ * E_];
    for (int idx = threadIdx.x; idx < C_ * E_; idx += 256) Ps[idx] = P[idx];
    __syncthreads();

    int r    = blockIdx.x * 8 + (threadIdx.x >> 5);
    int lane = threadIdx.x & 31;
    size_t off = (size_t)r * E_ + lane * 8;
    uint4 hv = *reinterpret_cast<const uint4*>(g_shi + off);
    uint4 lv = *reinterpret_cast<const uint4*>(g_slo + off);
    const __nv_bfloat16* hp = reinterpret_cast<const __nv_bfloat16*>(&hv);
    const __nv_bfloat16* lp = reinterpret_cast<const __nv_bfloat16*>(&lv);
    float x[8];
#pragma unroll
    for (int t = 0; t < 8; t++)
        x[t] = __bfloat162float(hp[t]) + __bfloat162float(lp[t]);
    const int e0 = lane * 8;

    float acc[C_];
#pragma unroll
    for (int c = 0; c < C_; c++) {
        const float* pc = &Ps[c * E_ + e0];
        float s = 0.f;
#pragma unroll
        for (int t = 0; t < 8; t++) s = fmaf(x[t], pc[t], s);
        acc[c] = s;
    }
#pragma unroll
    for (int c = 0; c < C_; c++) {
#pragma unroll
        for (int o = 16; o > 0; o >>= 1)
            acc[c] += __shfl_xor_sync(0xffffffffu, acc[c], o);
    }
    if (lane == 0) {
#pragma unroll
        for (int c = 0; c < C_; c++)
            out[(size_t)r * C_ + c] = acc[c] + pb[c];
    }
}

// ---------------------------------------------------------------------------
// Launch
// ---------------------------------------------------------------------------
extern "C" void kernel_launch(void* const* d_in, const int* in_sizes, int n_in,
                              void* d_out, int out_size) {
    const int*   words = (const int*)  d_in[0];
    const float* emb   = (const float*)d_in[1];
    const float* W     = (const float*)d_in[2];
    const float* bias  = (const float*)d_in[3];
    const float* P     = (const float*)d_in[4];
    const float* pb    = (const float*)d_in[5];
    float*       out   = (float*)d_out;

    static bool attr_done = false;
    if (!attr_done) {
        cudaFuncSetAttribute(mma_gemm, cudaFuncAttributeMaxDynamicSharedMemorySize,
                             SMEM_TOTAL);
        attr_done = true;
    }

    wsplit_kernel<<<(E_ * TWO_E) / 256, 256>>>(W);
    leaf_kernel<<<(B_ * L_) / 8, 256>>>(words, emb);

    int off = 0, n = L_;
    for (int l = 0; l < 9; l++) {
        int rpb = n >> 1;
        int lg  = 8 - l;
        int M   = B_ * rpb;
        dim3 grid(M / 128, 2);
        mma_gemm<<<grid, 256, SMEM_TOTAL>>>(bias, off, off + n, lg);
        off += n;
        n >>= 1;
    }

    proj_kernel<<<(B_ * NODES) / 8, 256>>>(P, pb, out);
}

// round 4
// speedup vs baseline: 2.3775x; 1.1663x over previous
#include <cuda_runtime.h>
#include <cuda_bf16.h>
#include <cstdint>

// ---------------------------------------------------------------------------
// Problem constants
// ---------------------------------------------------------------------------
#define B_     256
#define L_     512
#define E_     256
#define TWO_E  512
#define NODES  1023
#define SB     (NODES * E_)
#define C_     5

// Node states as split bf16 planes: value = hi + lo (~16 mantissa bits).
__device__ __nv_bfloat16 g_shi[(size_t)B_ * NODES * E_];
__device__ __nv_bfloat16 g_slo[(size_t)B_ * NODES * E_];
// W split into bf16 hi/lo, row-major (256 x 512).
__device__ __nv_bfloat16 g_Whi[E_ * TWO_E];
__device__ __nv_bfloat16 g_Wlo[E_ * TWO_E];

// ---------------------------------------------------------------------------
// Helpers
// ---------------------------------------------------------------------------
__device__ __forceinline__ uint32_t smem_u32(const void* p) {
    uint32_t a;
    asm("{ .reg .u64 t; cvta.to.shared.u64 t, %1; cvt.u32.u64 %0, t; }" : "=r"(a) : "l"(p));
    return a;
}
__device__ __forceinline__ uint32_t pkbf(__nv_bfloat16 a, __nv_bfloat16 b) {
    return (uint32_t)__bfloat16_as_ushort(a) | ((uint32_t)__bfloat16_as_ushort(b) << 16);
}

#define CP16(dst, src) \
    asm volatile("cp.async.ca.shared.global [%0], [%1], 16;" :: "r"(dst), "l"(src))
#define CP_COMMIT() asm volatile("cp.async.commit_group;" ::: "memory")

#define LDSM_X4(r, addr)                                                        \
    asm volatile("ldmatrix.sync.aligned.m8n8.x4.shared.b16 {%0,%1,%2,%3}, [%4];" \
        : "=r"((r)[0]), "=r"((r)[1]), "=r"((r)[2]), "=r"((r)[3]) : "r"(addr))

#define MMA16816(acc, a, b)                                                     \
    asm volatile("mma.sync.aligned.m16n8k16.row.col.f32.bf16.bf16.f32 "         \
        "{%0,%1,%2,%3}, {%4,%5,%6,%7}, {%8,%9}, {%0,%1,%2,%3};"                 \
        : "+f"((acc)[0]), "+f"((acc)[1]), "+f"((acc)[2]), "+f"((acc)[3])        \
        : "r"((a)[0]), "r"((a)[1]), "r"((a)[2]), "r"((a)[3]),                   \
          "r"((b)[0]), "r"((b)[1]))

#define ROWB 80                       // bytes per smem row: 32 bf16 + 8 pad

// ---------------------------------------------------------------------------
// init_out: out[b, n, c] = pb[c]  (atomic targets accumulate onto this)
// ---------------------------------------------------------------------------
__global__ void init_out(const float* __restrict__ pb, float* __restrict__ out) {
    size_t idx = (size_t)blockIdx.x * 256 + threadIdx.x;
    if (idx < (size_t)B_ * NODES * C_)
        out[idx] = pb[idx % C_];
}

// ---------------------------------------------------------------------------
// W split kernel: fp32 -> (hi, lo) bf16
// ---------------------------------------------------------------------------
__global__ void wsplit_kernel(const float* __restrict__ W) {
    int i = blockIdx.x * 256 + threadIdx.x;
    float f = W[i];
    __nv_bfloat16 h = __float2bfloat16(f);
    g_Whi[i] = h;
    g_Wlo[i] = __float2bfloat16(f - __bfloat162float(h));
}

// ---------------------------------------------------------------------------
// Leaves: relu(emb[word]) -> hi/lo planes + fused projection (direct store)
// ---------------------------------------------------------------------------
__global__ __launch_bounds__(256)
void leaf_kernel(const int* __restrict__ words, const float* __restrict__ emb,
                 const float* __restrict__ P, const float* __restrict__ pb,
                 float* __restrict__ out) {
    __shared__ float Ps[C_ * E_];
    __shared__ float pbs[C_];
    for (int idx = threadIdx.x; idx < C_ * E_; idx += 256) Ps[idx] = P[idx];
    if (threadIdx.x < C_) pbs[threadIdx.x] = pb[threadIdx.x];
    __syncthreads();

    int r    = blockIdx.x * 8 + (threadIdx.x >> 5);
    int lane = threadIdx.x & 31;
    int w = __ldg(&words[r]);
    const float4* src = reinterpret_cast<const float4*>(emb + (size_t)w * E_);
    float4 v0 = src[lane * 2], v1 = src[lane * 2 + 1];
    float x[8] = {fmaxf(v0.x, 0.f), fmaxf(v0.y, 0.f), fmaxf(v0.z, 0.f), fmaxf(v0.w, 0.f),
                  fmaxf(v1.x, 0.f), fmaxf(v1.y, 0.f), fmaxf(v1.z, 0.f), fmaxf(v1.w, 0.f)};
    uint32_t hi[4], lo[4];
#pragma unroll
    for (int p = 0; p < 4; p++) {
        __nv_bfloat16 ha = __float2bfloat16(x[2 * p]), hb = __float2bfloat16(x[2 * p + 1]);
        hi[p] = pkbf(ha, hb);
        lo[p] = pkbf(__float2bfloat16(x[2 * p]     - __bfloat162float(ha)),
                     __float2bfloat16(x[2 * p + 1] - __bfloat162float(hb)));
    }
    int b = r >> 9, i = r & 511;
    size_t off = (size_t)b * SB + (size_t)i * E_ + lane * 8;
    *reinterpret_cast<uint4*>(g_shi + off) = make_uint4(hi[0], hi[1], hi[2], hi[3]);
    *reinterpret_cast<uint4*>(g_slo + off) = make_uint4(lo[0], lo[1], lo[2], lo[3]);

    // fused projection: 5 dots over the full row
    float acc[C_];
#pragma unroll
    for (int c = 0; c < C_; c++) {
        const float* pc = &Ps[c * E_ + lane * 8];
        float s = 0.f;
#pragma unroll
        for (int t = 0; t < 8; t++) s = fmaf(x[t], pc[t], s);
        acc[c] = s;
    }
#pragma unroll
    for (int c = 0; c < C_; c++)
#pragma unroll
        for (int o = 16; o > 0; o >>= 1)
            acc[c] += __shfl_xor_sync(0xffffffffu, acc[c], o);
    if (lane == 0) {
        float* orow = out + ((size_t)b * NODES + i) * C_;
#pragma unroll
        for (int c = 0; c < C_; c++) orow[c] = acc[c] + pbs[c];
    }
}

// ---------------------------------------------------------------------------
// Compose GEMM (mma.sync bf16, split hi/lo, 3 products) + fused projection.
// CTA tile BM x 128 (grid.y = 2 covers N=256), 8 warps (4 x 2).
// 4-stage cp.async pipeline over K=512 in BK=32 chunks.
// Template: BM (128 or 64), MT = BM/64, NCH = chunks/thread, PLA = A plane bytes.
// ---------------------------------------------------------------------------
template <int BM, int MT, int NCH, int PLA>
__global__ __launch_bounds__(256, 1)
void mma_gemm(const float* __restrict__ bias, const float* __restrict__ P,
              float* __restrict__ out, int in_off, int out_off, int lg) {
    constexpr int OFF_AH = 0;
    constexpr int OFF_AL = PLA;
    constexpr int OFF_BH = 2 * PLA;
    constexpr int OFF_BL = 2 * PLA + 10240;
    constexpr int STAGE  = 2 * PLA + 20480;
    constexpr int SMB    = 4 * STAGE;          // bias: 128 floats
    constexpr int SMP    = SMB + 512;          // P tile: 5 x 128 floats

    extern __shared__ char smem[];
    const uint32_t sb = smem_u32(smem);
    const int tid  = threadIdx.x;
    const int lane = tid & 31;
    const int warp = tid >> 5;
    const int warpM = warp & 3;
    const int warpN = warp >> 2;
    const int blockRow = blockIdx.x * BM;
    const int colBase  = blockIdx.y * 128;
    const int msk = (1 << lg) - 1;

    if (tid < 128)
        reinterpret_cast<float*>(smem + SMB)[tid] = bias[colBase + tid];
    for (int j = tid; j < C_ * 128; j += 256)
        reinterpret_cast<float*>(smem + SMP)[j] = P[(j >> 7) * E_ + colBase + (j & 127)];

    // --- per-thread cp.async chunk descriptors (NCH x 16B per stage) ---
    const __nv_bfloat16* srcs[NCH];
    uint32_t dsts[NCH];
#pragma unroll
    for (int j = 0; j < NCH; j++) {
        int c = tid + 256 * j;
        if (c < BM * 8) {               // A: BM rows x 64B x 2 planes
            int plane = c / (BM * 4), row = (c >> 2) % BM, seg = c & 3;
            int gr = blockRow + row, ab = gr >> lg, ai = gr & msk;
            const __nv_bfloat16* g = plane ? g_slo : g_shi;
            srcs[j] = g + (size_t)ab * SB + (size_t)in_off * E_
                        + (size_t)ai * TWO_E + seg * 8;
            dsts[j] = (plane ? OFF_AL : OFF_AH) + row * ROWB + seg * 16;
        } else {                        // B: 128 W-rows x 64B x 2 planes
            int c2 = c - BM * 8;
            int plane = c2 >> 9, row = (c2 >> 2) & 127, seg = c2 & 3;
            const __nv_bfloat16* g = plane ? g_Wlo : g_Whi;
            srcs[j] = g + (size_t)(colBase + row) * TWO_E + seg * 8;
            dsts[j] = (plane ? OFF_BL : OFF_BH) + row * ROWB + seg * 16;
        }
    }

#define ISSUE(it) do {                                              \
        uint32_t _base = sb + ((it) & 3) * STAGE;                   \
        int _k0 = (it) * 32;                                        \
        _Pragma("unroll")                                           \
        for (int _j = 0; _j < NCH; _j++)                            \
            CP16(_base + dsts[_j], srcs[_j] + _k0);                 \
        CP_COMMIT();                                                \
    } while (0)

    ISSUE(0); ISSUE(1); ISSUE(2);

    float acc[MT][8][4];
#pragma unroll
    for (int mt = 0; mt < MT; mt++)
#pragma unroll
        for (int nt = 0; nt < 8; nt++)
#pragma unroll
            for (int q = 0; q < 4; q++) acc[mt][nt][q] = 0.f;

    const int aRow     = warpM * (16 * MT) + ((lane >> 3) & 1) * 8 + (lane & 7);
    const int aColHalf = (lane >> 4);
    const int bRow     = warpN * 64 + ((lane >> 4) << 3) + (lane & 7);
    const int bColHalf = (lane >> 3) & 1;

    for (int it = 0; it < 16; ++it) {
        if (it <= 13)      asm volatile("cp.async.wait_group 2;" ::: "memory");
        else if (it == 14) asm volatile("cp.async.wait_group 1;" ::: "memory");
        else               asm volatile("cp.async.wait_group 0;" ::: "memory");
        __syncthreads();
        if (it + 3 < 16) ISSUE(it + 3);
        uint32_t base = sb + (it & 3) * STAGE;

#pragma unroll
        for (int kk = 0; kk < 2; kk++) {
            uint32_t Ah[MT][4], Al[MT][4], Bh[8][2], Bl[8][2];
#pragma unroll
            for (int mt = 0; mt < MT; mt++) {
                uint32_t addr = base + (uint32_t)((aRow + mt * 16) * ROWB
                              + (kk * 16 + aColHalf * 8) * 2);
                LDSM_X4(Ah[mt], addr + OFF_AH);
                LDSM_X4(Al[mt], addr + OFF_AL);
            }
#pragma unroll
            for (int ntp = 0; ntp < 4; ntp++) {
                uint32_t addr = base + (uint32_t)((bRow + ntp * 16) * ROWB
                              + (kk * 16 + bColHalf * 8) * 2);
                uint32_t r0[4], r1[4];
                LDSM_X4(r0, addr + OFF_BH);
                LDSM_X4(r1, addr + OFF_BL);
                Bh[2 * ntp][0] = r0[0]; Bh[2 * ntp][1] = r0[1];
                Bh[2 * ntp + 1][0] = r0[2]; Bh[2 * ntp + 1][1] = r0[3];
                Bl[2 * ntp][0] = r1[0]; Bl[2 * ntp][1] = r1[1];
                Bl[2 * ntp + 1][0] = r1[2]; Bl[2 * ntp + 1][1] = r1[3];
            }
#pragma unroll
            for (int mt = 0; mt < MT; mt++)
#pragma unroll
                for (int nt = 0; nt < 8; nt++) {
                    MMA16816(acc[mt][nt], Ah[mt], Bh[nt]);
                    MMA16816(acc[mt][nt], Ah[mt], Bl[nt]);
                    MMA16816(acc[mt][nt], Al[mt], Bh[nt]);
                }
        }
    }
#undef ISSUE

    // --- epilogue: +bias, relu, split hi/lo store, fused partial projection ---
    const float* sbias = reinterpret_cast<const float*>(smem + SMB);
    const float* Ps2   = reinterpret_cast<const float*>(smem + SMP);
    const int nOff = warpN * 64 + (lane & 3) * 2;
#pragma unroll
    for (int mt = 0; mt < MT; mt++) {
        int rl = warpM * (16 * MT) + mt * 16 + (lane >> 2);
#pragma unroll
        for (int h = 0; h < 2; h++) {
            int gro = blockRow + rl + 8 * h;
            int ob = gro >> lg, oi = gro & msk;
            size_t rowoff = (size_t)ob * SB + (size_t)(out_off + oi) * E_
                          + colBase + nOff;
            uint32_t* dh = reinterpret_cast<uint32_t*>(g_shi + rowoff);
            uint32_t* dl = reinterpret_cast<uint32_t*>(g_slo + rowoff);
            float p5[C_] = {0.f, 0.f, 0.f, 0.f, 0.f};
#pragma unroll
            for (int nt = 0; nt < 8; nt++) {
                float v0 = fmaxf(acc[mt][nt][2 * h]     + sbias[nOff + nt * 8], 0.f);
                float v1 = fmaxf(acc[mt][nt][2 * h + 1] + sbias[nOff + nt * 8 + 1], 0.f);
                __nv_bfloat16 h0 = __float2bfloat16(v0), h1 = __float2bfloat16(v1);
                dh[nt * 4] = pkbf(h0, h1);
                dl[nt * 4] = pkbf(__float2bfloat16(v0 - __bfloat162float(h0)),
                                  __float2bfloat16(v1 - __bfloat162float(h1)));
                int cl = nOff + nt * 8;
#pragma unroll
                for (int c = 0; c < C_; c++)
                    p5[c] += v0 * Ps2[c * 128 + cl] + v1 * Ps2[c * 128 + cl + 1];
            }
#pragma unroll
            for (int c = 0; c < C_; c++) {
                p5[c] += __shfl_xor_sync(0xffffffffu, p5[c], 1);
                p5[c] += __shfl_xor_sync(0xffffffffu, p5[c], 2);
            }
            if ((lane & 3) == 0) {
                float* orow = out + ((size_t)ob * NODES + out_off + oi) * C_;
#pragma unroll
                for (int c = 0; c < C_; c++) atomicAdd(&orow[c], p5[c]);
            }
        }
    }
}

// ---------------------------------------------------------------------------
// Launch
// ---------------------------------------------------------------------------
#define SM128_TOTAL (4 * 40960 + 512 + 2560)   // 166912
#define SM64_TOTAL  (4 * 30720 + 512 + 2560)   // 125952

extern "C" void kernel_launch(void* const* d_in, const int* in_sizes, int n_in,
                              void* d_out, int out_size) {
    const int*   words = (const int*)  d_in[0];
    const float* emb   = (const float*)d_in[1];
    const float* W     = (const float*)d_in[2];
    const float* bias  = (const float*)d_in[3];
    const float* P     = (const float*)d_in[4];
    const float* pb    = (const float*)d_in[5];
    float*       out   = (float*)d_out;

    static bool attr_done = false;
    if (!attr_done) {
        cudaFuncSetAttribute(mma_gemm<128, 2, 8, 10240>,
                             cudaFuncAttributeMaxDynamicSharedMemorySize, SM128_TOTAL);
        cudaFuncSetAttribute(mma_gemm<64, 1, 6, 5120>,
                             cudaFuncAttributeMaxDynamicSharedMemorySize, SM64_TOTAL);
        attr_done = true;
    }

    init_out<<<(B_ * NODES * C_ + 255) / 256, 256>>>(pb, out);
    wsplit_kernel<<<(E_ * TWO_E) / 256, 256>>>(W);
    leaf_kernel<<<(B_ * L_) / 8, 256>>>(words, emb, P, pb, out);

    int off = 0, n = L_;
    for (int l = 0; l < 9; l++) {
        int rpb = n >> 1;
        int lg  = 8 - l;
        int M   = B_ * rpb;
        if (l < 4) {
            dim3 grid(M / 128, 2);
            mma_gemm<128, 2, 8, 10240><<<grid, 256, SM128_TOTAL>>>(
                bias, P, out, off, off + n, lg);
        } else {
            dim3 grid(M / 64, 2);
            mma_gemm<64, 1, 6, 5120><<<grid, 256, SM64_TOTAL>>>(
                bias, P, out, off, off + n, lg);
        }
        off += n;
        n >>= 1;
    }
}